// round 8
// baseline (speedup 1.0000x reference)
#include <cuda_runtime.h>
#include <cstdint>

#define FEAT_DIM     1024
#define ROWS_PER_BLK 8
#define BLK_THREADS  256
#define MAX_BLOCKS   (65536 / ROWS_PER_BLK)   // 8192

// Static scratch (allocation-free per harness rules)
__device__ float        g_partials[MAX_BLOCKS];
__device__ unsigned int g_done;   // self-resetting last-block counter

// ---------------------------------------------------------------------------
// Fully fused center loss, one launch. Key change vs round 6: feature loads
// are front-batched into a register array (MLP_p1 = 8 per lane) and the
// register cap is 64 (launch_bounds 256x4 = exactly the full RF), keeping
// occupancy at 32 warps/SM while eliminating exposed DRAM latency.
// ---------------------------------------------------------------------------
__global__ void __launch_bounds__(BLK_THREADS, 4)
center_loss_fused(const float* __restrict__ feat,
                  const float* __restrict__ centers,
                  const unsigned int* __restrict__ label_words,
                  float* __restrict__ out,
                  int batch, int num_classes, int nblocks) {
    const int warp = threadIdx.x >> 5;
    const int lane = threadIdx.x & 31;
    const int row  = blockIdx.x * ROWS_PER_BLK + warp;

    // ---- per-warp dtype probe (2 cache lines, L1/L2-hot after first warp) ----
    // int64 little-endian labels in [0,96) => all odd 32-bit words are 0.
    // int32 labels with 32 consecutive zero odd-words: prob ~ (1/96)^32 ~ 0.
    unsigned int oddw = label_words[2 * lane + 1];
    unsigned int any  = __ballot_sync(0xffffffffu, oddw != 0u);
    const int is64 = (any == 0u);

    int label = 0;
    if (lane == 0)
        label = is64 ? (int)label_words[2 * row] : (int)label_words[row];
    label = __shfl_sync(0xffffffffu, label, 0);

    const float4* fr = (const float4*)(feat    + (size_t)row   * FEAT_DIM);
    const float4* cr = (const float4*)(centers + (size_t)label * FEAT_DIM);

    // ---- front-batch ALL 8 feature LDG.128 (DRAM stream, MLP=8) ----
    float4 a[8];
    #pragma unroll
    for (int i = 0; i < 8; i++)
        a[i] = fr[lane + 32 * i];

    // ---- consume against L1/L2-hot center loads ----
    float acc = 0.0f;
    #pragma unroll
    for (int i = 0; i < 8; i++) {
        float4 b = cr[lane + 32 * i];
        float dx = a[i].x - b.x, dy = a[i].y - b.y;
        float dz = a[i].z - b.z, dw = a[i].w - b.w;
        acc = fmaf(dx, dx, acc);
        acc = fmaf(dy, dy, acc);
        acc = fmaf(dz, dz, acc);
        acc = fmaf(dw, dw, acc);
    }

    #pragma unroll
    for (int o = 16; o > 0; o >>= 1)
        acc += __shfl_xor_sync(0xffffffffu, acc, o);

    __shared__ float s[ROWS_PER_BLK];
    if (lane == 0)
        s[warp] = fminf(fmaxf(acc, 1e-12f), 1e12f);   // clip(d, 1e-12, 1e12)
    __syncthreads();

    // ---- per-block partial (fixed order -> deterministic) ----
    __shared__ unsigned int s_last;
    if (threadIdx.x == 0) {
        float t = 0.0f;
        #pragma unroll
        for (int i = 0; i < ROWS_PER_BLK; i++) t += s[i];
        g_partials[blockIdx.x] = t;
        __threadfence();
        unsigned int v = atomicAdd(&g_done, 1u);
        s_last = (v == (unsigned int)(nblocks - 1)) ? 1u : 0u;
    }
    __syncthreads();

    // ---- last block: deterministic double-precision final reduce ----
    if (s_last) {
        __threadfence();   // acquire: observe all g_partials writes
        double dacc = 0.0;
        for (int i = threadIdx.x; i < nblocks; i += BLK_THREADS)
            dacc += (double)g_partials[i];

        __shared__ double sd[BLK_THREADS];
        sd[threadIdx.x] = dacc;
        __syncthreads();
        #pragma unroll
        for (int st = BLK_THREADS / 2; st > 0; st >>= 1) {
            if (threadIdx.x < st) sd[threadIdx.x] += sd[threadIdx.x + st];
            __syncthreads();
        }
        if (threadIdx.x == 0) {
            g_done = 0;   // reset for next graph replay (deterministic state)
            out[0] = (float)(sd[0] / (double)batch
                             + (double)(num_classes - 1) * 1e-12);
        }
    }
}

// ---------------------------------------------------------------------------
extern "C" void kernel_launch(void* const* d_in, const int* in_sizes, int n_in,
                              void* d_out, int out_size) {
    const float*        feat    = (const float*)d_in[0];
    const float*        centers = (const float*)d_in[1];
    const unsigned int* labels  = (const unsigned int*)d_in[2];

    const int batch       = in_sizes[0] / FEAT_DIM;   // 65536
    const int num_classes = in_sizes[1] / FEAT_DIM;   // 96
    const int nblocks     = batch / ROWS_PER_BLK;     // 8192

    center_loss_fused<<<nblocks, BLK_THREADS>>>(feat, centers, labels,
                                                (float*)d_out,
                                                batch, num_classes, nblocks);
}

// round 9
// speedup vs baseline: 1.1416x; 1.1416x over previous
#include <cuda_runtime.h>
#include <cstdint>

#define FEAT_DIM     1024
#define ROWS_PER_BLK 8
#define BLK_THREADS  256
#define MAX_BLOCKS   (65536 / ROWS_PER_BLK)   // 8192

// Static scratch (allocation-free per harness rules)
__device__ float        g_partials[MAX_BLOCKS];
__device__ unsigned int g_done;   // self-resetting last-block counter

// ---------------------------------------------------------------------------
// Fully fused center loss, one launch. Round 9: two half-batches of 4
// front-batched feature LDG.128 (MLP_p1 = 4) inside a strict 32-register
// budget so occupancy stays at 64 warps/SM (the round-8 lesson: 64 warps
// beats per-warp MLP on this kernel; this takes both).
// ---------------------------------------------------------------------------
__global__ void __launch_bounds__(BLK_THREADS, 8)
center_loss_fused(const float* __restrict__ feat,
                  const float* __restrict__ centers,
                  const unsigned int* __restrict__ label_words,
                  float* __restrict__ out,
                  int batch, int num_classes, int nblocks) {
    const int warp = threadIdx.x >> 5;
    const int lane = threadIdx.x & 31;
    const int row  = blockIdx.x * ROWS_PER_BLK + warp;

    // ---- per-warp dtype probe (2 cache lines, L1/L2-hot after first warp) ----
    // int64 little-endian labels in [0,96) => all odd 32-bit words are 0.
    // int32 labels with 32 consecutive zero odd-words: prob ~ (1/96)^32 ~ 0.
    unsigned int oddw = label_words[2 * lane + 1];
    unsigned int any  = __ballot_sync(0xffffffffu, oddw != 0u);
    const int is64 = (any == 0u);

    int label = 0;
    if (lane == 0)
        label = is64 ? (int)label_words[2 * row] : (int)label_words[row];
    label = __shfl_sync(0xffffffffu, label, 0);

    const float4* fr = (const float4*)(feat    + (size_t)row   * FEAT_DIM) + lane;
    const float4* cr = (const float4*)(centers + (size_t)label * FEAT_DIM) + lane;

    float acc = 0.0f;
    #pragma unroll
    for (int h = 0; h < 2; h++) {          // two half-batches
        float4 a[4];
        #pragma unroll
        for (int i = 0; i < 4; i++)        // 4 feature LDG.128 in flight
            a[i] = fr[128 * h + 32 * i];
        #pragma unroll
        for (int i = 0; i < 4; i++) {      // consume vs L1/L2-hot center loads
            float4 b = cr[128 * h + 32 * i];
            float dx = a[i].x - b.x, dy = a[i].y - b.y;
            float dz = a[i].z - b.z, dw = a[i].w - b.w;
            acc = fmaf(dx, dx, acc);
            acc = fmaf(dy, dy, acc);
            acc = fmaf(dz, dz, acc);
            acc = fmaf(dw, dw, acc);
        }
    }

    #pragma unroll
    for (int o = 16; o > 0; o >>= 1)
        acc += __shfl_xor_sync(0xffffffffu, acc, o);

    __shared__ float s[ROWS_PER_BLK];
    if (lane == 0)
        s[warp] = fminf(fmaxf(acc, 1e-12f), 1e12f);   // clip(d, 1e-12, 1e12)
    __syncthreads();

    // ---- per-block partial (fixed order -> deterministic) ----
    __shared__ unsigned int s_last;
    if (threadIdx.x == 0) {
        float t = 0.0f;
        #pragma unroll
        for (int i = 0; i < ROWS_PER_BLK; i++) t += s[i];
        g_partials[blockIdx.x] = t;
        __threadfence();
        unsigned int v = atomicAdd(&g_done, 1u);
        s_last = (v == (unsigned int)(nblocks - 1)) ? 1u : 0u;
    }
    __syncthreads();

    // ---- last block: deterministic double-precision final reduce ----
    if (s_last) {
        __threadfence();   // acquire: observe all g_partials writes
        double dacc = 0.0;
        for (int i = threadIdx.x; i < nblocks; i += BLK_THREADS)
            dacc += (double)g_partials[i];

        __shared__ double sd[BLK_THREADS];
        sd[threadIdx.x] = dacc;
        __syncthreads();
        #pragma unroll
        for (int st = BLK_THREADS / 2; st > 0; st >>= 1) {
            if (threadIdx.x < st) sd[threadIdx.x] += sd[threadIdx.x + st];
            __syncthreads();
        }
        if (threadIdx.x == 0) {
            g_done = 0;   // reset for next graph replay (deterministic state)
            out[0] = (float)(sd[0] / (double)batch
                             + (double)(num_classes - 1) * 1e-12);
        }
    }
}

// ---------------------------------------------------------------------------
extern "C" void kernel_launch(void* const* d_in, const int* in_sizes, int n_in,
                              void* d_out, int out_size) {
    const float*        feat    = (const float*)d_in[0];
    const float*        centers = (const float*)d_in[1];
    const unsigned int* labels  = (const unsigned int*)d_in[2];

    const int batch       = in_sizes[0] / FEAT_DIM;   // 65536
    const int num_classes = in_sizes[1] / FEAT_DIM;   // 96
    const int nblocks     = batch / ROWS_PER_BLK;     // 8192

    center_loss_fused<<<nblocks, BLK_THREADS>>>(feat, centers, labels,
                                                (float*)d_out,
                                                batch, num_classes, nblocks);
}

// round 10
// speedup vs baseline: 1.3299x; 1.1649x over previous
#include <cuda_runtime.h>
#include <cstdint>

#define FEAT_DIM    1024
#define BLK_THREADS 256
#define WARPS_BLK   (BLK_THREADS / 32)
#define GRID_BLKS   1216            // 152 SMs x 8 blocks -> exactly one wave
#define MAX_BLOCKS  2048

// Static scratch (allocation-free per harness rules)
__device__ float        g_partials[MAX_BLOCKS];
__device__ unsigned int g_done;     // self-resetting last-block counter

// ---------------------------------------------------------------------------
// Persistent single-wave fused center loss. Each warp owns ~7 rows
// (stride = total warps), prefetches the NEXT row's label while computing the
// current row (hides the label->center dependent chain), streams features
// with .cs (evict-first) so L1 retains the 384 KB center set.
// ---------------------------------------------------------------------------
__global__ void __launch_bounds__(BLK_THREADS, 7)
center_loss_persist(const float* __restrict__ feat,
                    const float* __restrict__ centers,
                    const unsigned int* __restrict__ lw,
                    float* __restrict__ out,
                    int batch, int num_classes, int nblocks) {
    const int warp   = threadIdx.x >> 5;
    const int lane   = threadIdx.x & 31;
    const int gw     = blockIdx.x * WARPS_BLK + warp;
    const int nwarps = nblocks * WARPS_BLK;

    // ---- per-warp dtype probe (2 cache lines, hot after first warp) ----
    // int64 LE labels in [0,96) => all odd 32-bit words are 0.
    // False-positive for genuine int32 labels ~ (1/96)^32 ~ 0.
    unsigned int oddw = lw[2 * lane + 1];
    unsigned int any  = __ballot_sync(0xffffffffu, oddw != 0u);
    const int is64 = (any == 0u);

    float wsum = 0.0f;                 // per-warp running sum (fixed order)
    int r = gw;

    // first label (dependent chain exposed only once per warp)
    int lbl = 0;
    if (r < batch) {
        int l = 0;
        if (lane == 0) l = is64 ? (int)lw[2 * r] : (int)lw[r];
        lbl = __shfl_sync(0xffffffffu, l, 0);
    }

    while (r < batch) {
        // prefetch next row's label NOW; latency hidden under this row's work
        const int rn = r + nwarps;
        int lbln = 0;
        if (rn < batch) {
            int l = 0;
            if (lane == 0) l = is64 ? (int)lw[2 * rn] : (int)lw[rn];
            lbln = __shfl_sync(0xffffffffu, l, 0);
        }

        const float4* fr = (const float4*)(feat    + (size_t)r   * FEAT_DIM) + lane;
        const float4* cr = (const float4*)(centers + (size_t)lbl * FEAT_DIM) + lane;

        float acc = 0.0f;
        #pragma unroll
        for (int h = 0; h < 2; h++) {
            float4 a[4];
            #pragma unroll
            for (int i = 0; i < 4; i++)          // streaming: evict-first
                a[i] = __ldcs(&fr[128 * h + 32 * i]);
            #pragma unroll
            for (int i = 0; i < 4; i++) {        // centers: default (L1-retained)
                float4 b = cr[128 * h + 32 * i];
                float dx = a[i].x - b.x, dy = a[i].y - b.y;
                float dz = a[i].z - b.z, dw = a[i].w - b.w;
                acc = fmaf(dx, dx, acc);
                acc = fmaf(dy, dy, acc);
                acc = fmaf(dz, dz, acc);
                acc = fmaf(dw, dw, acc);
            }
        }

        #pragma unroll
        for (int o = 16; o > 0; o >>= 1)
            acc += __shfl_xor_sync(0xffffffffu, acc, o);

        // clip(d, 1e-12, 1e12) per row, then accumulate (fixed order)
        wsum += fminf(fmaxf(acc, 1e-12f), 1e12f);

        r = rn;
        lbl = lbln;
    }

    __shared__ float s[WARPS_BLK];
    if (lane == 0) s[warp] = wsum;
    __syncthreads();

    // ---- per-block partial (fixed order -> deterministic) ----
    __shared__ unsigned int s_last;
    if (threadIdx.x == 0) {
        float t = 0.0f;
        #pragma unroll
        for (int i = 0; i < WARPS_BLK; i++) t += s[i];
        g_partials[blockIdx.x] = t;
        __threadfence();
        unsigned int v = atomicAdd(&g_done, 1u);
        s_last = (v == (unsigned int)(nblocks - 1)) ? 1u : 0u;
    }
    __syncthreads();

    // ---- last block: deterministic double-precision final reduce ----
    if (s_last) {
        __threadfence();   // acquire: observe all g_partials writes
        double dacc = 0.0;
        for (int i = threadIdx.x; i < nblocks; i += BLK_THREADS)
            dacc += (double)g_partials[i];

        __shared__ double sd[BLK_THREADS];
        sd[threadIdx.x] = dacc;
        __syncthreads();
        #pragma unroll
        for (int st = BLK_THREADS / 2; st > 0; st >>= 1) {
            if (threadIdx.x < st) sd[threadIdx.x] += sd[threadIdx.x + st];
            __syncthreads();
        }
        if (threadIdx.x == 0) {
            g_done = 0;   // reset for next graph replay (deterministic state)
            out[0] = (float)(sd[0] / (double)batch
                             + (double)(num_classes - 1) * 1e-12);
        }
    }
}

// ---------------------------------------------------------------------------
extern "C" void kernel_launch(void* const* d_in, const int* in_sizes, int n_in,
                              void* d_out, int out_size) {
    const float*        feat    = (const float*)d_in[0];
    const float*        centers = (const float*)d_in[1];
    const unsigned int* labels  = (const unsigned int*)d_in[2];

    const int batch       = in_sizes[0] / FEAT_DIM;   // 65536
    const int num_classes = in_sizes[1] / FEAT_DIM;   // 96

    center_loss_persist<<<GRID_BLKS, BLK_THREADS>>>(feat, centers, labels,
                                                    (float*)d_out,
                                                    batch, num_classes,
                                                    GRID_BLKS);
}